// round 4
// baseline (speedup 1.0000x reference)
#include <cuda_runtime.h>
#include <math.h>

// ---------------- problem dims ----------------
#define F_  1024
#define H_  16
#define D_  18
#define P_  64
#define B_  128
#define T_  8192      // B*P tokens
#define C3F 3072
#define NC  23
#define MH  4096

// ---------------- device scratch (no runtime allocation allowed) ----------------
__device__ float g_qln[2][F_];                 // LN'd queries: [0]=channel, [1]=cls
__device__ float g_qh[2][F_];                  // projected queries (H*HD flat)
__device__ float g_wkeff[2][H_ * F_];          // folded key weights per head
__device__ float g_bkeff[2][H_];               // folded key bias per head
__device__ float g_mixed[(size_t)H_ * T_ * F_];// [h][t][f]  (512 MB)
__device__ float g_pooled[(size_t)T_ * F_];    // stage1 pooled (pre out-proj)
__device__ float g_z[(size_t)T_ * F_];         // pooled @ ch_out_w + b
__device__ float g_kv[(size_t)T_ * F_];        // ln(ln(z,cn),pnp)
__device__ float g_mixed2[H_ * B_ * F_];       // [h][b][f]
__device__ float g_pooled2[B_ * F_];
__device__ float g_p2[B_ * F_];
__device__ float g_p2ln[B_ * F_];
__device__ float g_hid[B_ * MH];

// ---------------- helpers ----------------
__device__ __forceinline__ float block_sum_256(float v, float* red) {
    #pragma unroll
    for (int o = 16; o; o >>= 1) v += __shfl_xor_sync(0xffffffffu, v, o);
    int w = threadIdx.x >> 5;
    if ((threadIdx.x & 31) == 0) red[w] = v;
    __syncthreads();
    float s = red[0];
    #pragma unroll
    for (int i = 1; i < 8; i++) s += red[i];
    __syncthreads();
    return s;
}

// ---------------- generic 1024-wide row LayerNorm ----------------
__global__ __launch_bounds__(256) void k_ln_row(const float* __restrict__ src,
                                                const float* __restrict__ g,
                                                const float* __restrict__ b,
                                                float* __restrict__ dst) {
    __shared__ float red[8];
    size_t row = blockIdx.x;
    int tid = threadIdx.x;
    float4 v = ((const float4*)src)[row * 256 + tid];
    float m = block_sum_256(v.x + v.y + v.z + v.w, red) * (1.f / 1024.f);
    float dx = v.x - m, dy = v.y - m, dz = v.z - m, dw = v.w - m;
    float var = block_sum_256(dx*dx + dy*dy + dz*dz + dw*dw, red) * (1.f / 1024.f);
    float rs = rsqrtf(var + 1e-5f);
    float4 gv = ((const float4*)g)[tid];
    float4 bv = ((const float4*)b)[tid];
    float4 o;
    o.x = dx * rs * gv.x + bv.x;
    o.y = dy * rs * gv.y + bv.y;
    o.z = dz * rs * gv.z + bv.z;
    o.w = dw * rs * gv.w + bv.w;
    ((float4*)dst)[row * 256 + tid] = o;
}

// ---------------- qh = q_ln @ W[:, :F] + b[:F], both sides ----------------
__global__ __launch_bounds__(128) void k_qh(const float* __restrict__ chw,
                                            const float* __restrict__ chb,
                                            const float* __restrict__ tw,
                                            const float* __restrict__ tb) {
    int side = blockIdx.y;
    const float* W  = side ? tw : chw;
    const float* bb = side ? tb : chb;
    const float* q  = g_qln[side];
    __shared__ float qs[F_];
    int tid = threadIdx.x;
    for (int i = tid; i < F_; i += 128) qs[i] = q[i];
    __syncthreads();
    int j = blockIdx.x * 128 + tid;
    float a0 = 0.f, a1 = 0.f, a2 = 0.f, a3 = 0.f;
    for (int f = 0; f < F_; f += 4) {
        a0 = fmaf(qs[f    ], W[(size_t)(f    ) * C3F + j], a0);
        a1 = fmaf(qs[f + 1], W[(size_t)(f + 1) * C3F + j], a1);
        a2 = fmaf(qs[f + 2], W[(size_t)(f + 2) * C3F + j], a2);
        a3 = fmaf(qs[f + 3], W[(size_t)(f + 3) * C3F + j], a3);
    }
    g_qh[side][j] = a0 + a1 + a2 + a3 + bb[j];
}

// ---------------- fold qh into W_k: wkeff[h][f], bkeff[h] ----------------
__global__ __launch_bounds__(128) void k_fold(const float* __restrict__ chw,
                                              const float* __restrict__ chb,
                                              const float* __restrict__ tw,
                                              const float* __restrict__ tb) {
    int side = blockIdx.y, f = blockIdx.x, tid = threadIdx.x;
    const float* W  = side ? tw : chw;
    const float* qh = g_qh[side];
    __shared__ float wrow[F_];
    for (int i = tid; i < F_; i += 128) wrow[i] = W[(size_t)f * C3F + F_ + i];
    __syncthreads();
    int h = tid >> 3, i8 = tid & 7;
    float s = 0.f;
    #pragma unroll
    for (int d = 0; d < 8; d++) s += wrow[h * 64 + i8 * 8 + d] * qh[h * 64 + i8 * 8 + d];
    s += __shfl_down_sync(0xffffffffu, s, 4, 8);
    s += __shfl_down_sync(0xffffffffu, s, 2, 8);
    s += __shfl_down_sync(0xffffffffu, s, 1, 8);
    if (i8 == 0) g_wkeff[side][h * F_ + f] = s;
    if (f == 0 && tid < H_) {
        const float* bb = side ? tb : chb;
        float bs = 0.f;
        for (int d = 0; d < 64; d++) bs += bb[F_ + tid * 64 + d] * qh[tid * 64 + d];
        g_bkeff[side][tid] = bs;
    }
}

// ---------------- fused main pass: scores -> softmax(D) -> channel mix ----------------
// grid (P, B), 256 threads. dyn smem: xs[18*1024] wk[16*1024] sc[288] attnT[288]
#define SMEM_MAIN ((D_ * F_ + H_ * F_ + 288 + 288) * 4)
__global__ __launch_bounds__(256) void k_main(const float* __restrict__ x) {
    extern __shared__ float sm[];
    float* xs    = sm;
    float* wk    = xs + D_ * F_;
    float* sc    = wk + H_ * F_;
    float* attnT = sc + 288;

    int p = blockIdx.x, b = blockIdx.y;
    int tid = threadIdx.x;
    int t = b * P_ + p;

    const float4* xg = (const float4*)x;
    #pragma unroll
    for (int k = 0; k < D_; k++)
        ((float4*)xs)[k * 256 + tid] = xg[((size_t)(b * D_ + k) * P_ + p) * 256 + tid];
    const float4* wg = (const float4*)g_wkeff[0];
    #pragma unroll
    for (int i = 0; i < 16; i++) {
        int idx = tid + i * 256;
        ((float4*)wk)[idx] = wg[idx];
    }
    __syncthreads();

    // scores: 288 (h,k) pairs over 8 warps
    int w = tid >> 5, lane = tid & 31;
    for (int j = 0; j < 36; j++) {
        int pair = w + 8 * j;
        int h = pair / D_, k = pair % D_;
        const float4* xr = (const float4*)(xs + k * F_);
        const float4* wr = (const float4*)(wk + h * F_);
        float s = 0.f;
        #pragma unroll
        for (int i = 0; i < 8; i++) {
            float4 a = xr[lane + 32 * i];
            float4 bv = wr[lane + 32 * i];
            s = fmaf(a.x, bv.x, s); s = fmaf(a.y, bv.y, s);
            s = fmaf(a.z, bv.z, s); s = fmaf(a.w, bv.w, s);
        }
        #pragma unroll
        for (int o = 16; o; o >>= 1) s += __shfl_xor_sync(0xffffffffu, s, o);
        if (lane == 0) sc[pair] = (s + g_bkeff[0][h]) * 0.125f;
    }
    __syncthreads();

    if (tid < H_) {
        int h = tid;
        float mx = -1e30f;
        #pragma unroll
        for (int k = 0; k < D_; k++) mx = fmaxf(mx, sc[h * D_ + k]);
        float e[D_], ssum = 0.f;
        #pragma unroll
        for (int k = 0; k < D_; k++) { e[k] = expf(sc[h * D_ + k] - mx); ssum += e[k]; }
        float inv = 1.f / ssum;
        #pragma unroll
        for (int k = 0; k < D_; k++) attnT[k * H_ + h] = e[k] * inv;   // transposed
    }
    __syncthreads();

    // mixed[h][f] = sum_k attn[h][k] * xs[k][f]
    float4 acc[H_];
    #pragma unroll
    for (int h = 0; h < H_; h++) acc[h] = make_float4(0.f, 0.f, 0.f, 0.f);
    #pragma unroll
    for (int k = 0; k < D_; k++) {
        float4 xv = ((const float4*)xs)[k * 256 + tid];
        const float4* at = (const float4*)(attnT + k * H_);
        float4 q0 = at[0], q1 = at[1], q2 = at[2], q3 = at[3];
        float av[16] = { q0.x, q0.y, q0.z, q0.w, q1.x, q1.y, q1.z, q1.w,
                         q2.x, q2.y, q2.z, q2.w, q3.x, q3.y, q3.z, q3.w };
        #pragma unroll
        for (int h = 0; h < H_; h++) {
            acc[h].x = fmaf(av[h], xv.x, acc[h].x);
            acc[h].y = fmaf(av[h], xv.y, acc[h].y);
            acc[h].z = fmaf(av[h], xv.z, acc[h].z);
            acc[h].w = fmaf(av[h], xv.w, acc[h].w);
        }
    }
    #pragma unroll
    for (int h = 0; h < H_; h++)
        ((float4*)g_mixed)[((size_t)h * T_ + t) * 256 + tid] = acc[h];
}

// ---------------- generic tiled SGEMM: C = A@B + bias, optional exact GELU ----------------
// BM=128 BN=64 BK=16, 256 threads, 8x4 per thread. M%128==0, N%64==0, K%16==0.
__global__ __launch_bounds__(256) void k_gemm(
    const float* __restrict__ A, int lda, long long sA,
    const float* __restrict__ Bm, int ldb, long long sB,
    const float* __restrict__ bias, long long sBias,
    float* __restrict__ C, int ldc, long long sC,
    int K, int act) {
    __shared__ float As[128 * 16];
    __shared__ float Bs[16 * 64];
    long long z = blockIdx.z;
    A += z * sA; Bm += z * sB; C += z * sC; bias += z * sBias;
    int tM = blockIdx.y * 128, tN = blockIdx.x * 64;
    int tid = threadIdx.x, tn = tid & 15, tm = tid >> 4;
    float acc[8][4];
    #pragma unroll
    for (int i = 0; i < 8; i++)
        #pragma unroll
        for (int j = 0; j < 4; j++) acc[i][j] = 0.f;

    for (int k0 = 0; k0 < K; k0 += 16) {
        #pragma unroll
        for (int i = 0; i < 2; i++) {
            int lin = tid + i * 256;
            int r = lin >> 2, c4 = lin & 3;
            float4 v = *(const float4*)(A + (size_t)(tM + r) * lda + k0 + c4 * 4);
            *(float4*)(As + r * 16 + c4 * 4) = v;
        }
        {
            int r = tid >> 4, c4 = tid & 15;
            float4 v = *(const float4*)(Bm + (size_t)(k0 + r) * ldb + tN + c4 * 4);
            *(float4*)(Bs + r * 64 + c4 * 4) = v;
        }
        __syncthreads();
        #pragma unroll
        for (int kk = 0; kk < 16; kk++) {
            float4 bf = *(const float4*)(Bs + kk * 64 + tn * 4);
            #pragma unroll
            for (int mi = 0; mi < 8; mi++) {
                float a = As[(tm * 8 + mi) * 16 + kk];
                acc[mi][0] = fmaf(a, bf.x, acc[mi][0]);
                acc[mi][1] = fmaf(a, bf.y, acc[mi][1]);
                acc[mi][2] = fmaf(a, bf.z, acc[mi][2]);
                acc[mi][3] = fmaf(a, bf.w, acc[mi][3]);
            }
        }
        __syncthreads();
    }
    float4 bv = *(const float4*)(bias + tN + tn * 4);
    #pragma unroll
    for (int mi = 0; mi < 8; mi++) {
        int row = tM + tm * 8 + mi;
        float4 o;
        o.x = acc[mi][0] + bv.x; o.y = acc[mi][1] + bv.y;
        o.z = acc[mi][2] + bv.z; o.w = acc[mi][3] + bv.w;
        if (act) {
            o.x = 0.5f * o.x * (1.f + erff(o.x * 0.70710678118654752f));
            o.y = 0.5f * o.y * (1.f + erff(o.y * 0.70710678118654752f));
            o.z = 0.5f * o.z * (1.f + erff(o.z * 0.70710678118654752f));
            o.w = 0.5f * o.w * (1.f + erff(o.w * 0.70710678118654752f));
        }
        *(float4*)(C + (size_t)row * ldc + tN + tn * 4) = o;
    }
}

// ---------------- kv = ln(ln(z, cn), pnp) ----------------
__global__ __launch_bounds__(256) void k_lnln(const float* __restrict__ g1,
                                              const float* __restrict__ b1,
                                              const float* __restrict__ g2,
                                              const float* __restrict__ b2) {
    __shared__ float red[8];
    size_t row = blockIdx.x;
    int tid = threadIdx.x;
    float4 v = ((const float4*)g_z)[row * 256 + tid];
    float m = block_sum_256(v.x + v.y + v.z + v.w, red) * (1.f / 1024.f);
    float dx = v.x - m, dy = v.y - m, dz = v.z - m, dw = v.w - m;
    float var = block_sum_256(dx*dx + dy*dy + dz*dz + dw*dw, red) * (1.f / 1024.f);
    float rs = rsqrtf(var + 1e-5f);
    float4 g1v = ((const float4*)g1)[tid], b1v = ((const float4*)b1)[tid];
    float yx = dx * rs * g1v.x + b1v.x, yy = dy * rs * g1v.y + b1v.y;
    float yz = dz * rs * g1v.z + b1v.z, yw = dw * rs * g1v.w + b1v.w;
    float m2 = block_sum_256(yx + yy + yz + yw, red) * (1.f / 1024.f);
    float ex = yx - m2, ey = yy - m2, ez = yz - m2, ew = yw - m2;
    float var2 = block_sum_256(ex*ex + ey*ey + ez*ez + ew*ew, red) * (1.f / 1024.f);
    float rs2 = rsqrtf(var2 + 1e-5f);
    float4 g2v = ((const float4*)g2)[tid], b2v = ((const float4*)b2)[tid];
    float4 o;
    o.x = ex * rs2 * g2v.x + b2v.x;
    o.y = ey * rs2 * g2v.y + b2v.y;
    o.z = ez * rs2 * g2v.z + b2v.z;
    o.w = ew * rs2 * g2v.w + b2v.w;
    ((float4*)g_kv)[row * 256 + tid] = o;
}

// ---------------- stage-2: scores over P, softmax, temporal mix ----------------
__global__ __launch_bounds__(256) void k_sc2mix() {
    __shared__ float sc[H_ * P_];
    int b = blockIdx.x, tid = threadIdx.x, w = tid >> 5, lane = tid & 31;
    for (int j = 0; j < 128; j++) {
        int pair = w + 8 * j;                  // 0..1023
        int h = pair >> 6, p = pair & 63;
        const float4* kr = (const float4*)(g_kv + (size_t)(b * P_ + p) * F_);
        const float4* wr = (const float4*)(g_wkeff[1] + h * F_);
        float s = 0.f;
        #pragma unroll
        for (int i = 0; i < 8; i++) {
            float4 a = kr[lane + 32 * i];
            float4 bv = wr[lane + 32 * i];
            s = fmaf(a.x, bv.x, s); s = fmaf(a.y, bv.y, s);
            s = fmaf(a.z, bv.z, s); s = fmaf(a.w, bv.w, s);
        }
        #pragma unroll
        for (int o = 16; o; o >>= 1) s += __shfl_xor_sync(0xffffffffu, s, o);
        if (lane == 0) sc[h * P_ + p] = (s + g_bkeff[1][h]) * 0.125f;
    }
    __syncthreads();
    if (tid < H_) {
        int h = tid;
        float mx = -1e30f;
        for (int p = 0; p < P_; p++) mx = fmaxf(mx, sc[h * P_ + p]);
        float ssum = 0.f;
        for (int p = 0; p < P_; p++) { float e = expf(sc[h * P_ + p] - mx); sc[h * P_ + p] = e; ssum += e; }
        float inv = 1.f / ssum;
        for (int p = 0; p < P_; p++) sc[h * P_ + p] *= inv;
    }
    __syncthreads();
    float4 acc[H_];
    #pragma unroll
    for (int h = 0; h < H_; h++) acc[h] = make_float4(0.f, 0.f, 0.f, 0.f);
    for (int p = 0; p < P_; p++) {
        float4 xv = ((const float4*)g_kv)[(size_t)(b * P_ + p) * 256 + tid];
        #pragma unroll
        for (int h = 0; h < H_; h++) {
            float a = sc[h * P_ + p];
            acc[h].x = fmaf(a, xv.x, acc[h].x);
            acc[h].y = fmaf(a, xv.y, acc[h].y);
            acc[h].z = fmaf(a, xv.z, acc[h].z);
            acc[h].w = fmaf(a, xv.w, acc[h].w);
        }
    }
    #pragma unroll
    for (int h = 0; h < H_; h++)
        ((float4*)g_mixed2)[(size_t)(h * B_ + b) * 256 + tid] = acc[h];
}

// ---------------- final classifier: logits = hid @ w2 + b2 ----------------
__global__ __launch_bounds__(256) void k_logits(const float* __restrict__ w2,
                                                const float* __restrict__ b2,
                                                float* __restrict__ out) {
    int b = blockIdx.x, tid = threadIdx.x, w = tid >> 5, lane = tid & 31;
    const float* hrow = g_hid + (size_t)b * MH;
    for (int c = w; c < NC; c += 8) {
        float s = 0.f;
        for (int i = lane; i < MH; i += 32) s = fmaf(hrow[i], w2[(size_t)i * NC + c], s);
        #pragma unroll
        for (int o = 16; o; o >>= 1) s += __shfl_xor_sync(0xffffffffu, s, o);
        if (lane == 0) out[b * NC + c] = s + b2[c];
    }
}

// ---------------- launch ----------------
extern "C" void kernel_launch(void* const* d_in, const int* in_sizes, int n_in,
                              void* d_out, int out_size) {
    (void)in_sizes; (void)n_in; (void)out_size;
    const float* x    = (const float*)d_in[0];
    const float* chq  = (const float*)d_in[1];
    const float* clq  = (const float*)d_in[2];
    const float* chw  = (const float*)d_in[3];
    const float* chb  = (const float*)d_in[4];
    const float* chow = (const float*)d_in[5];
    const float* chob = (const float*)d_in[6];
    const float* tw   = (const float*)d_in[7];
    const float* tb   = (const float*)d_in[8];
    const float* tow  = (const float*)d_in[9];
    const float* tob  = (const float*)d_in[10];
    const float* qn_g = (const float*)d_in[11];
    const float* qn_b = (const float*)d_in[12];
    const float* cn_g = (const float*)d_in[13];
    const float* cn_b = (const float*)d_in[14];
    const float* pnc_g = (const float*)d_in[15];
    const float* pnc_b = (const float*)d_in[16];
    const float* pnp_g = (const float*)d_in[17];
    const float* pnp_b = (const float*)d_in[18];
    const float* pon_g = (const float*)d_in[19];
    const float* pon_b = (const float*)d_in[20];
    const float* w1 = (const float*)d_in[21];
    const float* b1 = (const float*)d_in[22];
    const float* w2 = (const float*)d_in[23];
    const float* b2 = (const float*)d_in[24];
    float* out = (float*)d_out;

    float *p_qln, *p_mixed, *p_pooled, *p_z, *p_mixed2, *p_pooled2, *p_p2, *p_p2ln, *p_hid;
    cudaGetSymbolAddress((void**)&p_qln,     g_qln);
    cudaGetSymbolAddress((void**)&p_mixed,   g_mixed);
    cudaGetSymbolAddress((void**)&p_pooled,  g_pooled);
    cudaGetSymbolAddress((void**)&p_z,       g_z);
    cudaGetSymbolAddress((void**)&p_mixed2,  g_mixed2);
    cudaGetSymbolAddress((void**)&p_pooled2, g_pooled2);
    cudaGetSymbolAddress((void**)&p_p2,      g_p2);
    cudaGetSymbolAddress((void**)&p_p2ln,    g_p2ln);
    cudaGetSymbolAddress((void**)&p_hid,     g_hid);

    cudaFuncSetAttribute(k_main, cudaFuncAttributeMaxDynamicSharedMemorySize, SMEM_MAIN);

    // query LayerNorms
    k_ln_row<<<1, 256>>>(chq, qn_g, qn_b, p_qln);
    k_ln_row<<<1, 256>>>(clq, pnc_g, pnc_b, p_qln + F_);
    // project queries, fold into key weights
    k_qh<<<dim3(8, 2), 128>>>(chw, chb, tw, tb);
    k_fold<<<dim3(1024, 2), 128>>>(chw, chb, tw, tb);
    // stage 1 fused: scores + softmax + channel mix
    k_main<<<dim3(P_, B_), 256, SMEM_MAIN>>>(x);
    // pooled = mixed_h @ Wv_h + bv (batched over heads)
    k_gemm<<<dim3(1, T_ / 128, H_), 256>>>(p_mixed, F_, (long long)T_ * F_,
                                           chw + 2 * F_, C3F, 64,
                                           chb + 2 * F_, 64,
                                           p_pooled, F_, 64, F_, 0);
    // z = pooled @ ch_out_w + ch_out_b
    k_gemm<<<dim3(F_ / 64, T_ / 128, 1), 256>>>(p_pooled, F_, 0,
                                                chow, F_, 0, chob, 0,
                                                p_z, F_, 0, F_, 0);
    // kv = ln(ln(z, cn), pnp)
    k_lnln<<<T_, 256>>>(cn_g, cn_b, pnp_g, pnp_b);
    // stage 2 fused: temporal scores + softmax + mix
    k_sc2mix<<<B_, 256>>>();
    // pooled2 = mixed2_h @ Wv2_h + bv2
    k_gemm<<<dim3(1, 1, H_), 256>>>(p_mixed2, F_, (long long)B_ * F_,
                                    tw + 2 * F_, C3F, 64,
                                    tb + 2 * F_, 64,
                                    p_pooled2, F_, 64, F_, 0);
    // p2 = pooled2 @ t_out_w + t_out_b
    k_gemm<<<dim3(F_ / 64, 1, 1), 256>>>(p_pooled2, F_, 0,
                                         tow, F_, 0, tob, 0,
                                         p_p2, F_, 0, F_, 0);
    // p2ln = ln(p2, pon)
    k_ln_row<<<B_, 256>>>(p_p2, pon_g, pon_b, p_p2ln);
    // hid = gelu(p2ln @ w1 + b1)
    k_gemm<<<dim3(MH / 64, 1, 1), 256>>>(p_p2ln, F_, 0,
                                         w1, MH, 0, b1, 0,
                                         p_hid, MH, 0, F_, 1);
    // logits
    k_logits<<<B_, 256>>>(w2, b2, out);
}